// round 12
// baseline (speedup 1.0000x reference)
#include <cuda_runtime.h>
#include <cuda_fp16.h>
#include <cstdint>

// ---------------------------------------------------------------------------
// CodebookLayer: out[m] = codebook[argmax_c (2*x.c - ||c||^2)]
//
// Round 12: warp-specialized screen GEMM with 64x64 consumer tiles.
// 192 thr: warps 0-3 consumers (64x64, f16 acc), warps 4 (A) / 5 (B)
// producers. 6-stage mbarrier pipeline, no __syncthreads in mainloop.
// Exact fp64 rescore (MARGIN 6) unchanged.
// ---------------------------------------------------------------------------

#define MDIM 8192
#define CDIM 8192
#define KDIM 1024

__device__ __half g_scores[(size_t)MDIM * CDIM];   // 128 MB scratch
__device__ __half g_xh [(size_t)MDIM * KDIM];
__device__ __half g_ch [(size_t)CDIM * KDIM];
__device__ float  g_c2[CDIM];

// ---------------- helpers ---------------------------------------------------
__device__ __forceinline__ uint32_t smem_u32(const void* p) {
    uint32_t a;
    asm("{ .reg .u64 t; cvta.to.shared.u64 t, %1; cvt.u32.u64 %0, t; }"
        : "=r"(a) : "l"(p));
    return a;
}
__device__ __forceinline__ void cp16(uint32_t s, const void* g) {
    asm volatile("cp.async.cg.shared.global [%0], [%1], 16;"
                 :: "r"(s), "l"(g) : "memory");
}
__device__ __forceinline__ void ldsm4(uint32_t* r, uint32_t addr) {
    asm volatile("ldmatrix.sync.aligned.m8n8.x4.shared.b16 {%0,%1,%2,%3}, [%4];"
        : "=r"(r[0]), "=r"(r[1]), "=r"(r[2]), "=r"(r[3]) : "r"(addr));
}
__device__ __forceinline__ void mma_f16(uint32_t* d, const uint32_t* a,
                                        uint32_t b0, uint32_t b1) {
    asm volatile(
        "mma.sync.aligned.m16n8k16.row.col.f16.f16.f16.f16 "
        "{%0,%1}, {%2,%3,%4,%5}, {%6,%7}, {%0,%1};"
        : "+r"(d[0]), "+r"(d[1])
        : "r"(a[0]), "r"(a[1]), "r"(a[2]), "r"(a[3]), "r"(b0), "r"(b1));
}
__device__ __forceinline__ void mbar_init(uint32_t addr, uint32_t cnt) {
    asm volatile("mbarrier.init.shared.b64 [%0], %1;" :: "r"(addr), "r"(cnt) : "memory");
}
__device__ __forceinline__ void mbar_wait(uint32_t addr, uint32_t parity) {
    asm volatile(
        "{\n\t.reg .pred P;\n"
        "WL_%=:\n\t"
        "mbarrier.try_wait.parity.acquire.cta.shared::cta.b64 P, [%0], %1, 0x989680;\n\t"
        "@P bra WD_%=;\n\t"
        "bra WL_%=;\n"
        "WD_%=:\n\t}"
        :: "r"(addr), "r"(parity) : "memory");
}
__device__ __forceinline__ void mbar_arrive(uint32_t addr) {
    asm volatile("mbarrier.arrive.shared.b64 _, [%0];" :: "r"(addr) : "memory");
}
__device__ __forceinline__ void cpasync_mbar_arrive_noinc(uint32_t addr) {
    asm volatile("cp.async.mbarrier.arrive.noinc.shared.b64 [%0];"
                 :: "r"(addr) : "memory");
}

// ---------------- kernel 0: fp32 -> f16 --------------------------------------
__global__ void convert_kernel(const float* __restrict__ s,
                               __half* __restrict__ d, int n) {
    int i = (blockIdx.x * blockDim.x + threadIdx.x) * 4;
    if (i >= n) return;
    float4 v = *reinterpret_cast<const float4*>(s + i);
    __half2 p0 = __floats2half2_rn(v.x, v.y);
    __half2 p1 = __floats2half2_rn(v.z, v.w);
    *reinterpret_cast<__half2*>(d + i)     = p0;
    *reinterpret_cast<__half2*>(d + i + 2) = p1;
}

// ---------------- kernel 1: codebook row norms -------------------------------
__global__ void c2_kernel(const float* __restrict__ cb, int C, int K) {
    int row  = blockIdx.x * (blockDim.x >> 5) + (threadIdx.x >> 5);
    int lane = threadIdx.x & 31;
    if (row >= C) return;
    const float4* p = reinterpret_cast<const float4*>(cb + (size_t)row * K);
    float s = 0.f;
    for (int i = lane; i < (K >> 2); i += 32) {
        float4 v = p[i];
        s += v.x * v.x + v.y * v.y + v.z * v.z + v.w * v.w;
    }
    #pragma unroll
    for (int m = 16; m; m >>= 1) s += __shfl_xor_sync(0xffffffffu, s, m);
    if (lane == 0) g_c2[row] = s;
}

// ---------------- kernel 2: warp-specialized screening GEMM ------------------
// BM=BN=128, BK=32. 192 thr: warps 0-3 consumers (64x64, f16 acc),
// warps 4 (A) / 5 (B) producers. 6-stage mbarrier pipeline.
#define NSTAGE 6
#define STAGE_BYTES 16384          // A 8KB + B 8KB (128 rows x 64B)
#define NS (KDIM / 32)             // 32 k-stages
#define SMEM_TOT (1024 + NSTAGE * STAGE_BYTES)

__global__ __launch_bounds__(192, 2) void screen_gemm() {
    extern __shared__ __align__(1024) char smem[];
    const uint32_t base  = smem_u32(smem);
    const uint32_t mb    = base;                 // full[s]=+s*16, empty[s]=+s*16+8
    const uint32_t tiles = base + 1024;

    const int t    = threadIdx.x;
    const int lane = t & 31;
    const int wid  = t >> 5;
    const int bm   = blockIdx.y * 128;
    const int bn   = blockIdx.x * 128;

    if (t == 0) {
        #pragma unroll
        for (int s = 0; s < NSTAGE; s++) {
            mbar_init(mb + s * 16,     64);   // full: 2 prod warps x 32 noinc
            mbar_init(mb + s * 16 + 8, 4);    // empty: 4 consumer warp arrivals
        }
    }
    __syncthreads();

    if (wid >= 4) {
        // ================= PRODUCER (warp 4: A tile, warp 5: B tile) ========
        const int pw   = wid - 4;                        // 0=A, 1=B
        const int row0 = lane >> 2;                      // 0..7
        const int ch   = lane & 3;
        const __half* gsrc = (pw == 0)
            ? g_xh + (size_t)(bm + row0) * KDIM + ch * 8
            : g_ch + (size_t)(bn + row0) * KDIM + ch * 8;
        const uint32_t half_off = (uint32_t)pw * 8192u;
        const uint32_t w0 = (uint32_t)row0 * 64 +
                            (uint32_t)((ch ^ ((row0 >> 1) & 3)) << 4);

        int b = 0, ep = 0;
        for (int s = 0; s < NS; s++) {
            if (s >= NSTAGE) mbar_wait(mb + b * 16 + 8, ep);
            const uint32_t so = tiles + b * STAGE_BYTES + half_off;
            const __half* g = gsrc + s * 32;
            #pragma unroll
            for (int i = 0; i < 16; i++)
                cp16(so + w0 + i * 512, g + (size_t)i * 8 * KDIM);
            cpasync_mbar_arrive_noinc(mb + b * 16);
            if (++b == NSTAGE) { b = 0; if (s >= NSTAGE) ep ^= 1; }
        }
        return;                                          // producers done
    }

    // ===================== CONSUMER (warps 0-3, 64x64 tiles) ================
    const int wm = wid >> 1;            // 0..1
    const int wn = wid & 1;             // 0..1
    const int rbase = lane & 15;
    const uint32_t lh = (uint32_t)(lane >> 4);           // 0/1

    uint32_t a_off[4], a_x[4], b_off[4], b_x[4];
    #pragma unroll
    for (int mi = 0; mi < 4; mi++) {
        int row = wm * 64 + mi * 16 + rbase;
        a_off[mi] = (uint32_t)row * 64;
        a_x[mi]   = (uint32_t)((row >> 1) & 3);
    }
    #pragma unroll
    for (int g = 0; g < 4; g++) {
        int row = wn * 64 + g * 16 + rbase;
        b_off[g] = 8192u + (uint32_t)row * 64;
        b_x[g]   = (uint32_t)((row >> 1) & 3);
    }

    uint32_t acc[4][8][2];
    #pragma unroll
    for (int i = 0; i < 4; i++)
        #pragma unroll
        for (int j = 0; j < 8; j++) { acc[i][j][0] = 0u; acc[i][j][1] = 0u; }

    uint32_t af[2][4][4], bf[2][4][4];

    #define LOADK(pp, As, kk)                                                 \
        {                                                                     \
            uint32_t cin = (uint32_t)(2 * (kk)) | lh;                         \
            ldsm4(af[pp][0], (As) + a_off[0] + ((cin ^ a_x[0]) << 4));        \
            ldsm4(af[pp][1], (As) + a_off[1] + ((cin ^ a_x[1]) << 4));        \
            ldsm4(af[pp][2], (As) + a_off[2] + ((cin ^ a_x[2]) << 4));        \
            ldsm4(af[pp][3], (As) + a_off[3] + ((cin ^ a_x[3]) << 4));        \
            ldsm4(bf[pp][0], (As) + b_off[0] + ((cin ^ b_x[0]) << 4));        \
            ldsm4(bf[pp][1], (As) + b_off[1] + ((cin ^ b_x[1]) << 4));        \
            ldsm4(bf[pp][2], (As) + b_off[2] + ((cin ^ b_x[2]) << 4));        \
            ldsm4(bf[pp][3], (As) + b_off[3] + ((cin ^ b_x[3]) << 4));        \
        }
    #define MMAK(pp)                                                          \
        {                                                                     \
            _Pragma("unroll")                                                 \
            for (int mi = 0; mi < 4; mi++)                                    \
                _Pragma("unroll")                                             \
                for (int ni = 0; ni < 8; ni++)                                \
                    mma_f16(acc[mi][ni], af[pp][mi],                          \
                            bf[pp][ni >> 1][ni & 1],                          \
                            bf[pp][ni >> 1][(ni & 1) + 2]);                   \
        }

    int b = 0, pf = 0;
    for (int s = 0; s < NS; s++) {
        mbar_wait(mb + b * 16, pf);
        const uint32_t As = tiles + b * STAGE_BYTES;

        LOADK(0, As, 0)
        LOADK(1, As, 1)
        if (lane == 0) mbar_arrive(mb + b * 16 + 8);   // release after ldsm
        MMAK(0)
        MMAK(1)

        if (++b == NSTAGE) { b = 0; pf ^= 1; }
    }

    // ---- epilogue: score = 2*xc - c2 + 1024, fp16 store ----
    #pragma unroll
    for (int ni = 0; ni < 8; ni++) {
        int n0 = bn + wn * 64 + ni * 8 + 2 * (lane & 3);
        float c2a = 1024.f - g_c2[n0];
        float c2b = 1024.f - g_c2[n0 + 1];
        #pragma unroll
        for (int mi = 0; mi < 4; mi++) {
            int m0 = bm + wm * 64 + mi * 16 + (lane >> 2);
            float2 f0 = __half22float2(*reinterpret_cast<__half2*>(&acc[mi][ni][0]));
            float2 f1 = __half22float2(*reinterpret_cast<__half2*>(&acc[mi][ni][1]));
            __half2 h0 = __floats2half2_rn(2.f * f0.x + c2a, 2.f * f0.y + c2b);
            __half2 h1 = __floats2half2_rn(2.f * f1.x + c2a, 2.f * f1.y + c2b);
            *reinterpret_cast<__half2*>(&g_scores[(size_t)m0 * CDIM + n0])       = h0;
            *reinterpret_cast<__half2*>(&g_scores[(size_t)(m0 + 8) * CDIM + n0]) = h1;
        }
    }
}

// ---------------- kernel 3: select + exact fp64 rescore ----------------------
#define MARGIN 6.0f
#define MAXCAND 128

__global__ __launch_bounds__(256) void select_rescore(
    const float* __restrict__ x, const float* __restrict__ cb,
    float* __restrict__ out)
{
    __shared__ float  xs[KDIM];
    __shared__ float  smax[8];
    __shared__ double sred[2][8];
    __shared__ int    cand[MAXCAND];
    __shared__ int    ncand;

    const int m    = blockIdx.x;
    const int t    = threadIdx.x;
    const int lane = t & 31;
    const int wrp  = t >> 5;

    {
        const float4* src = reinterpret_cast<const float4*>(x + (size_t)m * KDIM);
        reinterpret_cast<float4*>(xs)[t] = src[t];
    }
    if (t == 0) ncand = 0;

    const uint4* row = reinterpret_cast<const uint4*>(g_scores + (size_t)m * CDIM);
    uint4 v[4];
    float lmax = -3.4e38f;
    #pragma unroll
    for (int j = 0; j < 4; j++) {
        v[j] = row[t + 256 * j];
        const __half2* h = reinterpret_cast<const __half2*>(&v[j]);
        #pragma unroll
        for (int e = 0; e < 4; e++) {
            float2 f = __half22float2(h[e]);
            lmax = fmaxf(lmax, fmaxf(f.x, f.y));
        }
    }
    #pragma unroll
    for (int o = 16; o; o >>= 1)
        lmax = fmaxf(lmax, __shfl_xor_sync(0xffffffffu, lmax, o));
    if (lane == 0) smax[wrp] = lmax;
    __syncthreads();
    float rowmax = smax[0];
    #pragma unroll
    for (int w = 1; w < 8; w++) rowmax = fmaxf(rowmax, smax[w]);
    const float thresh = rowmax - MARGIN;

    #pragma unroll
    for (int j = 0; j < 4; j++) {
        const __half2* h = reinterpret_cast<const __half2*>(&v[j]);
        #pragma unroll
        for (int e = 0; e < 4; e++) {
            float2 f = __half22float2(h[e]);
            int base = (t + 256 * j) * 8 + e * 2;
            if (f.x > thresh) { int p = atomicAdd(&ncand, 1); if (p < MAXCAND) cand[p] = base; }
            if (f.y > thresh) { int p = atomicAdd(&ncand, 1); if (p < MAXCAND) cand[p] = base + 1; }
        }
    }
    __syncthreads();
    int nc = min(ncand, MAXCAND);

    double bestS = -1e300;
    int    bestI = 0x7FFFFFFF;
    for (int ci = 0; ci < nc; ci++) {
        int c = cand[ci];
        const float* crow = cb + (size_t)c * KDIM;
        double s = 0.0, cc = 0.0;
        for (int d = t; d < KDIM; d += 256) {
            double cv = (double)crow[d];
            s  += (double)xs[d] * cv;
            cc += cv * cv;
        }
        #pragma unroll
        for (int o = 16; o; o >>= 1) {
            s  += __shfl_xor_sync(0xffffffffu, s,  o);
            cc += __shfl_xor_sync(0xffffffffu, cc, o);
        }
        if (lane == 0) { sred[0][wrp] = s; sred[1][wrp] = cc; }
        __syncthreads();
        double st = 0.0, ct = 0.0;
        #pragma unroll
        for (int w = 0; w < 8; w++) { st += sred[0][w]; ct += sred[1][w]; }
        __syncthreads();
        double sc = 2.0 * st - ct;
        if (sc > bestS || (sc == bestS && c < bestI)) { bestS = sc; bestI = c; }
    }

    const float4* src = reinterpret_cast<const float4*>(cb + (size_t)bestI * KDIM);
    float4* dst = reinterpret_cast<float4*>(out + (size_t)m * KDIM);
    dst[t] = src[t];
}

// ---------------- launch ------------------------------------------------------
extern "C" void kernel_launch(void* const* d_in, const int* in_sizes, int n_in,
                              void* d_out, int out_size)
{
    const float* x  = (const float*)d_in[0];   // [8192, 1024]
    const float* cb = (const float*)d_in[1];   // [8192, 1024]
    float* out = (float*)d_out;

    const int NX = MDIM * KDIM;
    const int NC = CDIM * KDIM;

    __half *xh_p = nullptr, *ch_p = nullptr;
    cudaGetSymbolAddress((void**)&xh_p, g_xh);
    cudaGetSymbolAddress((void**)&ch_p, g_ch);

    cudaFuncSetAttribute(screen_gemm,
                         cudaFuncAttributeMaxDynamicSharedMemorySize, SMEM_TOT);

    convert_kernel<<<NX / 1024, 256>>>(x,  xh_p, NX);
    convert_kernel<<<NC / 1024, 256>>>(cb, ch_p, NC);
    c2_kernel<<<CDIM / 8, 256>>>(cb, CDIM, KDIM);

    dim3 grid(CDIM / 128, MDIM / 128);
    screen_gemm<<<grid, 192, SMEM_TOT>>>();

    select_rescore<<<MDIM, 256>>>(x, cb, out);
}

// round 13
// speedup vs baseline: 1.0251x; 1.0251x over previous
#include <cuda_runtime.h>
#include <cuda_fp16.h>
#include <cstdint>

// ---------------------------------------------------------------------------
// CodebookLayer: out[m] = codebook[argmax_c (2*x.c - ||c||^2)]
//
// Round 13: R11 warp-specialized pipeline + cross-stage software pipelining:
// the full-barrier wait and first-half ldsm of stage s+1 are issued between
// the two MMA bursts of stage s (latency buried under 16 MMAs), and all
// ldsm swizzle offsets are precomputed. Exact fp64 rescore unchanged.
// ---------------------------------------------------------------------------

#define MDIM 8192
#define CDIM 8192
#define KDIM 1024

__device__ __half g_scores[(size_t)MDIM * CDIM];   // 128 MB scratch
__device__ __half g_xh [(size_t)MDIM * KDIM];
__device__ __half g_ch [(size_t)CDIM * KDIM];
__device__ float  g_c2[CDIM];

// ---------------- helpers ---------------------------------------------------
__device__ __forceinline__ uint32_t smem_u32(const void* p) {
    uint32_t a;
    asm("{ .reg .u64 t; cvta.to.shared.u64 t, %1; cvt.u32.u64 %0, t; }"
        : "=r"(a) : "l"(p));
    return a;
}
__device__ __forceinline__ void cp16(uint32_t s, const void* g) {
    asm volatile("cp.async.cg.shared.global [%0], [%1], 16;"
                 :: "r"(s), "l"(g) : "memory");
}
__device__ __forceinline__ void ldsm4(uint32_t* r, uint32_t addr) {
    asm volatile("ldmatrix.sync.aligned.m8n8.x4.shared.b16 {%0,%1,%2,%3}, [%4];"
        : "=r"(r[0]), "=r"(r[1]), "=r"(r[2]), "=r"(r[3]) : "r"(addr));
}
__device__ __forceinline__ void mma_f16(uint32_t* d, const uint32_t* a,
                                        uint32_t b0, uint32_t b1) {
    asm volatile(
        "mma.sync.aligned.m16n8k16.row.col.f16.f16.f16.f16 "
        "{%0,%1}, {%2,%3,%4,%5}, {%6,%7}, {%0,%1};"
        : "+r"(d[0]), "+r"(d[1])
        : "r"(a[0]), "r"(a[1]), "r"(a[2]), "r"(a[3]), "r"(b0), "r"(b1));
}
__device__ __forceinline__ void mbar_init(uint32_t addr, uint32_t cnt) {
    asm volatile("mbarrier.init.shared.b64 [%0], %1;" :: "r"(addr), "r"(cnt) : "memory");
}
__device__ __forceinline__ void mbar_wait(uint32_t addr, uint32_t parity) {
    asm volatile(
        "{\n\t.reg .pred P;\n"
        "WL_%=:\n\t"
        "mbarrier.try_wait.parity.acquire.cta.shared::cta.b64 P, [%0], %1, 0x989680;\n\t"
        "@P bra WD_%=;\n\t"
        "bra WL_%=;\n"
        "WD_%=:\n\t}"
        :: "r"(addr), "r"(parity) : "memory");
}
__device__ __forceinline__ void mbar_arrive(uint32_t addr) {
    asm volatile("mbarrier.arrive.release.cta.shared::cta.b64 _, [%0];"
                 :: "r"(addr) : "memory");
}
__device__ __forceinline__ void cpasync_mbar_arrive_noinc(uint32_t addr) {
    asm volatile("cp.async.mbarrier.arrive.noinc.shared.b64 [%0];"
                 :: "r"(addr) : "memory");
}

// ---------------- kernel 0: fp32 -> f16 --------------------------------------
__global__ void convert_kernel(const float* __restrict__ s,
                               __half* __restrict__ d, int n) {
    int i = (blockIdx.x * blockDim.x + threadIdx.x) * 4;
    if (i >= n) return;
    float4 v = *reinterpret_cast<const float4*>(s + i);
    __half2 p0 = __floats2half2_rn(v.x, v.y);
    __half2 p1 = __floats2half2_rn(v.z, v.w);
    *reinterpret_cast<__half2*>(d + i)     = p0;
    *reinterpret_cast<__half2*>(d + i + 2) = p1;
}

// ---------------- kernel 1: codebook row norms -------------------------------
__global__ void c2_kernel(const float* __restrict__ cb, int C, int K) {
    int row  = blockIdx.x * (blockDim.x >> 5) + (threadIdx.x >> 5);
    int lane = threadIdx.x & 31;
    if (row >= C) return;
    const float4* p = reinterpret_cast<const float4*>(cb + (size_t)row * K);
    float s = 0.f;
    for (int i = lane; i < (K >> 2); i += 32) {
        float4 v = p[i];
        s += v.x * v.x + v.y * v.y + v.z * v.z + v.w * v.w;
    }
    #pragma unroll
    for (int m = 16; m; m >>= 1) s += __shfl_xor_sync(0xffffffffu, s, m);
    if (lane == 0) g_c2[row] = s;
}

// ---------------- kernel 2: warp-specialized screening GEMM ------------------
// BM=BN=128, BK=32. 320 thr: warps 0-7 consumers (64x32 tiles, f16 acc),
// warps 8 (A) / 9 (B) producers. 6-stage mbarrier pipeline,
// cross-stage software pipelining in the consumer.
#define NSTAGE 6
#define STAGE_BYTES 16384          // A 8KB + B 8KB (128 rows x 64B)
#define NS (KDIM / 32)             // 32 k-stages
#define SMEM_TOT (1024 + NSTAGE * STAGE_BYTES)

__global__ __launch_bounds__(320, 2) void screen_gemm() {
    extern __shared__ __align__(1024) char smem[];
    const uint32_t base  = smem_u32(smem);
    const uint32_t mb    = base;                 // full[s]=+s*16, empty[s]=+s*16+8
    const uint32_t tiles = base + 1024;

    const int t    = threadIdx.x;
    const int lane = t & 31;
    const int wid  = t >> 5;
    const int bm   = blockIdx.y * 128;
    const int bn   = blockIdx.x * 128;

    if (t == 0) {
        #pragma unroll
        for (int s = 0; s < NSTAGE; s++) {
            mbar_init(mb + s * 16,     64);   // full: 2 prod warps x 32 noinc
            mbar_init(mb + s * 16 + 8, 8);    // empty: 8 consumer warp arrivals
        }
    }
    __syncthreads();

    if (wid >= 8) {
        // ================= PRODUCER (warp 8: A tile, warp 9: B tile) ========
        const int pw   = wid - 8;                        // 0=A, 1=B
        const int row0 = lane >> 2;                      // 0..7
        const int ch   = lane & 3;
        const __half* gsrc = (pw == 0)
            ? g_xh + (size_t)(bm + row0) * KDIM + ch * 8
            : g_ch + (size_t)(bn + row0) * KDIM + ch * 8;
        const uint32_t half_off = (uint32_t)pw * 8192u;
        const uint32_t w0 = (uint32_t)row0 * 64 +
                            (uint32_t)((ch ^ ((row0 >> 1) & 3)) << 4);

        int b = 0, ep = 0;
        for (int s = 0; s < NS; s++) {
            if (s >= NSTAGE) mbar_wait(mb + b * 16 + 8, ep);
            const uint32_t so = tiles + b * STAGE_BYTES + half_off;
            const __half* g = gsrc + s * 32;
            #pragma unroll
            for (int i = 0; i < 16; i++)
                cp16(so + w0 + i * 512, g + (size_t)i * 8 * KDIM);
            cpasync_mbar_arrive_noinc(mb + b * 16);
            if (++b == NSTAGE) { b = 0; if (s >= NSTAGE) ep ^= 1; }
        }
        return;                                          // producers done
    }

    // ===================== CONSUMER (warps 0-7, 64x32 tiles) ================
    const int wm = wid >> 2;            // 0..1
    const int wn = wid & 3;             // 0..3
    const int rbase = lane & 15;
    const uint32_t lh = (uint32_t)(lane >> 4);           // 0/1

    // precomputed swizzled ldsm offsets: [half][slot] (A slots 0-3, B slots 4-5)
    uint32_t off0[6], off1[6];
    #pragma unroll
    for (int mi = 0; mi < 4; mi++) {
        int row = wm * 64 + mi * 16 + rbase;
        uint32_t ao = (uint32_t)row * 64;
        uint32_t ax = (uint32_t)((row >> 1) & 3);
        off0[mi] = ao + (((0u | lh) ^ ax) << 4);
        off1[mi] = ao + (((2u | lh) ^ ax) << 4);
    }
    #pragma unroll
    for (int g = 0; g < 2; g++) {
        int row = wn * 32 + g * 16 + rbase;
        uint32_t bo = 8192u + (uint32_t)row * 64;
        uint32_t bx = (uint32_t)((row >> 1) & 3);
        off0[4 + g] = bo + (((0u | lh) ^ bx) << 4);
        off1[4 + g] = bo + (((2u | lh) ^ bx) << 4);
    }

    uint32_t acc[4][4][2];
    #pragma unroll
    for (int i = 0; i < 4; i++)
        #pragma unroll
        for (int j = 0; j < 4; j++) { acc[i][j][0] = 0u; acc[i][j][1] = 0u; }

    // F0 <- half 0 frags, F1 <- half 1 frags (fixed roles)
    uint32_t fa0[4][4], fb0[2][4], fa1[4][4], fb1[2][4];

    #define LOAD0(As)                                                         \
        {                                                                     \
            ldsm4(fa0[0], (As) + off0[0]); ldsm4(fa0[1], (As) + off0[1]);     \
            ldsm4(fa0[2], (As) + off0[2]); ldsm4(fa0[3], (As) + off0[3]);     \
            ldsm4(fb0[0], (As) + off0[4]); ldsm4(fb0[1], (As) + off0[5]);     \
        }
    #define LOAD1(As)                                                         \
        {                                                                     \
            ldsm4(fa1[0], (As) + off1[0]); ldsm4(fa1[1], (As) + off1[1]);     \
            ldsm4(fa1[2], (As) + off1[2]); ldsm4(fa1[3], (As) + off1[3]);     \
            ldsm4(fb1[0], (As) + off1[4]); ldsm4(fb1[1], (As) + off1[5]);     \
        }
    #define MMA0()                                                            \
        {                                                                     \
            _Pragma("unroll")                                                 \
            for (int mi = 0; mi < 4; mi++)                                    \
                _Pragma("unroll")                                             \
                for (int ni = 0; ni < 4; ni++)                                \
                    mma_f16(acc[mi][ni], fa0[mi],                             \
                            fb0[ni >> 1][ni & 1], fb0[ni >> 1][(ni & 1) + 2]);\
        }
    #define MMA1()                                                            \
        {                                                                     \
            _Pragma("unroll")                                                 \
            for (int mi = 0; mi < 4; mi++)                                    \
                _Pragma("unroll")                                             \
                for (int ni = 0; ni < 4; ni++)                                \
                    mma_f16(acc[mi][ni], fa1[mi],                             \
                            fb1[ni >> 1][ni & 1], fb1[ni >> 1][(ni & 1) + 2]);\
        }

    // prologue: stage 0 half 0
    int b = 0, pf = 0;
    mbar_wait(mb + 0, 0);
    LOAD0(tiles)

    for (int s = 0; s < NS; s++) {
        const uint32_t As = tiles + b * STAGE_BYTES;

        LOAD1(As)                                    // half 1 of stage s
        if (lane == 0) mbar_arrive(mb + b * 16 + 8); // all stage-s ldsm issued

        const int nb  = (b + 1 == NSTAGE) ? 0 : b + 1;
        const int npf = (b + 1 == NSTAGE) ? (pf ^ 1) : pf;

        MMA0()                                       // 16 MMAs cover latency

        if (s + 1 < NS) {
            mbar_wait(mb + nb * 16, npf);            // usually fast-path
            LOAD0(tiles + nb * STAGE_BYTES)          // half 0 of stage s+1
        }

        MMA1()                                       // 16 MMAs cover latency

        b = nb; pf = npf;
    }

    // ---- epilogue: score = 2*xc - c2 + 1024, fp16 store ----
    #pragma unroll
    for (int ni = 0; ni < 4; ni++) {
        int n0 = bn + wn * 32 + ni * 8 + 2 * (lane & 3);
        float c2a = 1024.f - g_c2[n0];
        float c2b = 1024.f - g_c2[n0 + 1];
        #pragma unroll
        for (int mi = 0; mi < 4; mi++) {
            int m0 = bm + wm * 64 + mi * 16 + (lane >> 2);
            float2 f0 = __half22float2(*reinterpret_cast<__half2*>(&acc[mi][ni][0]));
            float2 f1 = __half22float2(*reinterpret_cast<__half2*>(&acc[mi][ni][1]));
            __half2 h0 = __floats2half2_rn(2.f * f0.x + c2a, 2.f * f0.y + c2b);
            __half2 h1 = __floats2half2_rn(2.f * f1.x + c2a, 2.f * f1.y + c2b);
            *reinterpret_cast<__half2*>(&g_scores[(size_t)m0 * CDIM + n0])       = h0;
            *reinterpret_cast<__half2*>(&g_scores[(size_t)(m0 + 8) * CDIM + n0]) = h1;
        }
    }
}

// ---------------- kernel 3: select + exact fp64 rescore ----------------------
#define MARGIN 6.0f
#define MAXCAND 128

__global__ __launch_bounds__(256) void select_rescore(
    const float* __restrict__ x, const float* __restrict__ cb,
    float* __restrict__ out)
{
    __shared__ float  xs[KDIM];
    __shared__ float  smax[8];
    __shared__ double sred[2][8];
    __shared__ int    cand[MAXCAND];
    __shared__ int    ncand;

    const int m    = blockIdx.x;
    const int t    = threadIdx.x;
    const int lane = t & 31;
    const int wrp  = t >> 5;

    {
        const float4* src = reinterpret_cast<const float4*>(x + (size_t)m * KDIM);
        reinterpret_cast<float4*>(xs)[t] = src[t];
    }
    if (t == 0) ncand = 0;

    const uint4* row = reinterpret_cast<const uint4*>(g_scores + (size_t)m * CDIM);
    uint4 v[4];
    float lmax = -3.4e38f;
    #pragma unroll
    for (int j = 0; j < 4; j++) {
        v[j] = row[t + 256 * j];
        const __half2* h = reinterpret_cast<const __half2*>(&v[j]);
        #pragma unroll
        for (int e = 0; e < 4; e++) {
            float2 f = __half22float2(h[e]);
            lmax = fmaxf(lmax, fmaxf(f.x, f.y));
        }
    }
    #pragma unroll
    for (int o = 16; o; o >>= 1)
        lmax = fmaxf(lmax, __shfl_xor_sync(0xffffffffu, lmax, o));
    if (lane == 0) smax[wrp] = lmax;
    __syncthreads();
    float rowmax = smax[0];
    #pragma unroll
    for (int w = 1; w < 8; w++) rowmax = fmaxf(rowmax, smax[w]);
    const float thresh = rowmax - MARGIN;

    #pragma unroll
    for (int j = 0; j < 4; j++) {
        const __half2* h = reinterpret_cast<const __half2*>(&v[j]);
        #pragma unroll
        for (int e = 0; e < 4; e++) {
            float2 f = __half22float2(h[e]);
            int base = (t + 256 * j) * 8 + e * 2;
            if (f.x > thresh) { int p = atomicAdd(&ncand, 1); if (p < MAXCAND) cand[p] = base; }
            if (f.y > thresh) { int p = atomicAdd(&ncand, 1); if (p < MAXCAND) cand[p] = base + 1; }
        }
    }
    __syncthreads();
    int nc = min(ncand, MAXCAND);

    double bestS = -1e300;
    int    bestI = 0x7FFFFFFF;
    for (int ci = 0; ci < nc; ci++) {
        int c = cand[ci];
        const float* crow = cb + (size_t)c * KDIM;
        double s = 0.0, cc = 0.0;
        for (int d = t; d < KDIM; d += 256) {
            double cv = (double)crow[d];
            s  += (double)xs[d] * cv;
            cc += cv * cv;
        }
        #pragma unroll
        for (int o = 16; o; o >>= 1) {
            s  += __shfl_xor_sync(0xffffffffu, s,  o);
            cc += __shfl_xor_sync(0xffffffffu, cc, o);
        }
        if (lane == 0) { sred[0][wrp] = s; sred[1][wrp] = cc; }
        __syncthreads();
        double st = 0.0, ct = 0.0;
        #pragma unroll
        for (int w = 0; w < 8; w++) { st += sred[0][w]; ct += sred[1][w]; }
        __syncthreads();
        double sc = 2.0 * st - ct;
        if (sc > bestS || (sc == bestS && c < bestI)) { bestS = sc; bestI = c; }
    }

    const float4* src = reinterpret_cast<const float4*>(cb + (size_t)bestI * KDIM);
    float4* dst = reinterpret_cast<float4*>(out + (size_t)m * KDIM);
    dst[t] = src[t];
}

// ---------------- launch ------------------------------------------------------
extern "C" void kernel_launch(void* const* d_in, const int* in_sizes, int n_in,
                              void* d_out, int out_size)
{
    const float* x  = (const float*)d_in[0];   // [8192, 1024]
    const float* cb = (const float*)d_in[1];   // [8192, 1024]
    float* out = (float*)d_out;

    const int NX = MDIM * KDIM;
    const int NC = CDIM * KDIM;

    __half *xh_p = nullptr, *ch_p = nullptr;
    cudaGetSymbolAddress((void**)&xh_p, g_xh);
    cudaGetSymbolAddress((void**)&ch_p, g_ch);

    cudaFuncSetAttribute(screen_gemm,
                         cudaFuncAttributeMaxDynamicSharedMemorySize, SMEM_TOT);

    convert_kernel<<<NX / 1024, 256>>>(x,  xh_p, NX);
    convert_kernel<<<NC / 1024, 256>>>(cb, ch_p, NC);
    c2_kernel<<<CDIM / 8, 256>>>(cb, CDIM, KDIM);

    dim3 grid(CDIM / 128, MDIM / 128);
    screen_gemm<<<grid, 320, SMEM_TOT>>>();

    select_rescore<<<MDIM, 256>>>(x, cb, out);
}

// round 14
// speedup vs baseline: 1.5140x; 1.4770x over previous
#include <cuda_runtime.h>
#include <cuda_fp16.h>
#include <cstdint>

// ---------------------------------------------------------------------------
// CodebookLayer: out[m] = codebook[argmax_c (2*x.c - ||c||^2)]
//
// Round 14: INT8 IMMA screening GEMM (mma.m16n8k32.s8.s32, exact s32 acc),
// warp-specialized mbarrier pipeline (R13 skeleton), K=64 per stage.
// Quantization q=round(25*v); screen noise sigma~1; MARGIN=10.
// Exact fp64 rescore of candidates unchanged.
// ---------------------------------------------------------------------------

#define MDIM 8192
#define CDIM 8192
#define KDIM 1024
#define QSCALE 25.0f
#define DEQ (2.0f / (QSCALE * QSCALE))   // 2/625

__device__ __half  g_scores[(size_t)MDIM * CDIM];   // 128 MB scratch
__device__ int8_t  g_x8 [(size_t)MDIM * KDIM];
__device__ int8_t  g_cb8[(size_t)CDIM * KDIM];
__device__ float   g_c2[CDIM];

// ---------------- helpers ---------------------------------------------------
__device__ __forceinline__ uint32_t smem_u32(const void* p) {
    uint32_t a;
    asm("{ .reg .u64 t; cvta.to.shared.u64 t, %1; cvt.u32.u64 %0, t; }"
        : "=r"(a) : "l"(p));
    return a;
}
__device__ __forceinline__ void cp16(uint32_t s, const void* g) {
    asm volatile("cp.async.cg.shared.global [%0], [%1], 16;"
                 :: "r"(s), "l"(g) : "memory");
}
__device__ __forceinline__ void ldsm4(uint32_t* r, uint32_t addr) {
    asm volatile("ldmatrix.sync.aligned.m8n8.x4.shared.b16 {%0,%1,%2,%3}, [%4];"
        : "=r"(r[0]), "=r"(r[1]), "=r"(r[2]), "=r"(r[3]) : "r"(addr));
}
// int8 inputs, s32 accumulators (exact)
__device__ __forceinline__ void mma_s8(int* d, const uint32_t* a,
                                       uint32_t b0, uint32_t b1) {
    asm volatile(
        "mma.sync.aligned.m16n8k32.row.col.s32.s8.s8.s32 "
        "{%0,%1,%2,%3}, {%4,%5,%6,%7}, {%8,%9}, {%0,%1,%2,%3};"
        : "+r"(d[0]), "+r"(d[1]), "+r"(d[2]), "+r"(d[3])
        : "r"(a[0]), "r"(a[1]), "r"(a[2]), "r"(a[3]), "r"(b0), "r"(b1));
}
__device__ __forceinline__ void mbar_init(uint32_t addr, uint32_t cnt) {
    asm volatile("mbarrier.init.shared.b64 [%0], %1;" :: "r"(addr), "r"(cnt) : "memory");
}
__device__ __forceinline__ void mbar_wait(uint32_t addr, uint32_t parity) {
    asm volatile(
        "{\n\t.reg .pred P;\n"
        "WL_%=:\n\t"
        "mbarrier.try_wait.parity.acquire.cta.shared::cta.b64 P, [%0], %1, 0x989680;\n\t"
        "@P bra WD_%=;\n\t"
        "bra WL_%=;\n"
        "WD_%=:\n\t}"
        :: "r"(addr), "r"(parity) : "memory");
}
__device__ __forceinline__ void mbar_arrive(uint32_t addr) {
    asm volatile("mbarrier.arrive.release.cta.shared::cta.b64 _, [%0];"
                 :: "r"(addr) : "memory");
}
__device__ __forceinline__ void cpasync_mbar_arrive_noinc(uint32_t addr) {
    asm volatile("cp.async.mbarrier.arrive.noinc.shared.b64 [%0];"
                 :: "r"(addr) : "memory");
}

// ---------------- kernel 0: fp32 -> s8 (q = clamp(round(25 v))) --------------
__device__ __forceinline__ uint32_t q4(float4 v) {
    int a = __float2int_rn(v.x * QSCALE);
    int b = __float2int_rn(v.y * QSCALE);
    int c = __float2int_rn(v.z * QSCALE);
    int d = __float2int_rn(v.w * QSCALE);
    a = max(-127, min(127, a)); b = max(-127, min(127, b));
    c = max(-127, min(127, c)); d = max(-127, min(127, d));
    return (uint32_t)(uint8_t)a | ((uint32_t)(uint8_t)b << 8) |
           ((uint32_t)(uint8_t)c << 16) | ((uint32_t)(uint8_t)d << 24);
}
__global__ void convert_s8(const float* __restrict__ s,
                           int8_t* __restrict__ d, int n) {
    int i = (blockIdx.x * blockDim.x + threadIdx.x) * 8;
    if (i >= n) return;
    float4 v0 = *reinterpret_cast<const float4*>(s + i);
    float4 v1 = *reinterpret_cast<const float4*>(s + i + 4);
    uint2 o; o.x = q4(v0); o.y = q4(v1);
    *reinterpret_cast<uint2*>(d + i) = o;
}

// ---------------- kernel 1: codebook row norms (exact fp32) ------------------
__global__ void c2_kernel(const float* __restrict__ cb, int C, int K) {
    int row  = blockIdx.x * (blockDim.x >> 5) + (threadIdx.x >> 5);
    int lane = threadIdx.x & 31;
    if (row >= C) return;
    const float4* p = reinterpret_cast<const float4*>(cb + (size_t)row * K);
    float s = 0.f;
    for (int i = lane; i < (K >> 2); i += 32) {
        float4 v = p[i];
        s += v.x * v.x + v.y * v.y + v.z * v.z + v.w * v.w;
    }
    #pragma unroll
    for (int m = 16; m; m >>= 1) s += __shfl_xor_sync(0xffffffffu, s, m);
    if (lane == 0) g_c2[row] = s;
}

// ---------------- kernel 2: warp-specialized int8 screening GEMM -------------
// BM=BN=128, BK=64 int8 (64B rows). 320 thr: warps 0-7 consumers
// (64x32 tiles, s32 acc), warps 8 (A) / 9 (B) producers. 6-stage pipeline.
#define NSTAGE 6
#define STAGE_BYTES 16384          // A 8KB + B 8KB (128 rows x 64B)
#define NS (KDIM / 64)             // 16 k-stages
#define SMEM_TOT (1024 + NSTAGE * STAGE_BYTES)

__global__ __launch_bounds__(320, 2) void screen_gemm() {
    extern __shared__ __align__(1024) char smem[];
    const uint32_t base  = smem_u32(smem);
    const uint32_t mb    = base;                 // full[s]=+s*16, empty[s]=+s*16+8
    const uint32_t tiles = base + 1024;

    const int t    = threadIdx.x;
    const int lane = t & 31;
    const int wid  = t >> 5;
    const int bm   = blockIdx.y * 128;
    const int bn   = blockIdx.x * 128;

    if (t == 0) {
        #pragma unroll
        for (int s = 0; s < NSTAGE; s++) {
            mbar_init(mb + s * 16,     64);   // full: 2 prod warps x 32 noinc
            mbar_init(mb + s * 16 + 8, 8);    // empty: 8 consumer warp arrivals
        }
    }
    __syncthreads();

    if (wid >= 8) {
        // ================= PRODUCER (warp 8: A tile, warp 9: B tile) ========
        const int pw   = wid - 8;                        // 0=A, 1=B
        const int row0 = lane >> 2;                      // 0..7
        const int ch   = lane & 3;
        const int8_t* gsrc = (pw == 0)
            ? g_x8  + (size_t)(bm + row0) * KDIM + ch * 16
            : g_cb8 + (size_t)(bn + row0) * KDIM + ch * 16;
        const uint32_t half_off = (uint32_t)pw * 8192u;
        const uint32_t w0 = (uint32_t)row0 * 64 +
                            (uint32_t)((ch ^ ((row0 >> 1) & 3)) << 4);

        int b = 0, ep = 0;
        for (int s = 0; s < NS; s++) {
            if (s >= NSTAGE) mbar_wait(mb + b * 16 + 8, ep);
            const uint32_t so = tiles + b * STAGE_BYTES + half_off;
            const int8_t* g = gsrc + s * 64;
            #pragma unroll
            for (int i = 0; i < 16; i++)
                cp16(so + w0 + i * 512, g + (size_t)i * 8 * KDIM);
            cpasync_mbar_arrive_noinc(mb + b * 16);
            if (++b == NSTAGE) { b = 0; if (s >= NSTAGE) ep ^= 1; }
        }
        return;                                          // producers done
    }

    // ===================== CONSUMER (warps 0-7, 64x32 tiles) ================
    const int wm = wid >> 2;            // 0..1
    const int wn = wid & 3;             // 0..3
    const int rbase = lane & 15;
    const uint32_t lh = (uint32_t)(lane >> 4);           // 0/1

    // swizzled ldsm offsets for k32-half 0 (half 1 = off ^ 0x20)
    uint32_t off[6];
    #pragma unroll
    for (int mi = 0; mi < 4; mi++) {
        int row = wm * 64 + mi * 16 + rbase;
        off[mi] = (uint32_t)row * 64 +
                  (((0u | lh) ^ (uint32_t)((row >> 1) & 3)) << 4);
    }
    #pragma unroll
    for (int g = 0; g < 2; g++) {
        int row = wn * 32 + g * 16 + rbase;
        off[4 + g] = 8192u + (uint32_t)row * 64 +
                     (((0u | lh) ^ (uint32_t)((row >> 1) & 3)) << 4);
    }

    int acc[4][4][4];
    #pragma unroll
    for (int i = 0; i < 4; i++)
        #pragma unroll
        for (int j = 0; j < 4; j++)
            #pragma unroll
            for (int k = 0; k < 4; k++) acc[i][j][k] = 0;

    uint32_t fa[4][4], fb[2][4];

    #define LOADK(As, x)                                                      \
        {                                                                     \
            ldsm4(fa[0], (As) + (off[0] ^ (x))); ldsm4(fa[1], (As) + (off[1] ^ (x))); \
            ldsm4(fa[2], (As) + (off[2] ^ (x))); ldsm4(fa[3], (As) + (off[3] ^ (x))); \
            ldsm4(fb[0], (As) + (off[4] ^ (x))); ldsm4(fb[1], (As) + (off[5] ^ (x))); \
        }
    #define MMAK()                                                            \
        {                                                                     \
            _Pragma("unroll")                                                 \
            for (int mi = 0; mi < 4; mi++)                                    \
                _Pragma("unroll")                                             \
                for (int ni = 0; ni < 4; ni++)                                \
                    mma_s8(acc[mi][ni], fa[mi],                               \
                           fb[ni >> 1][ni & 1], fb[ni >> 1][(ni & 1) + 2]);   \
        }

    int b = 0, pf = 0;
    for (int s = 0; s < NS; s++) {
        mbar_wait(mb + b * 16, pf);
        const uint32_t As = tiles + b * STAGE_BYTES;

        LOADK(As, 0u)                                 // k32 half 0
        MMAK()
        LOADK(As, 0x20u)                              // k32 half 1
        if (lane == 0) mbar_arrive(mb + b * 16 + 8);  // all stage ldsm done
        MMAK()

        if (++b == NSTAGE) { b = 0; pf ^= 1; }
    }

    // ---- epilogue: score = DEQ*qdot + (1024 - c2), fp16 store ----
    #pragma unroll
    for (int ni = 0; ni < 4; ni++) {
        int n0 = bn + wn * 32 + ni * 8 + 2 * (lane & 3);
        float c2a = 1024.f - g_c2[n0];
        float c2b = 1024.f - g_c2[n0 + 1];
        #pragma unroll
        for (int mi = 0; mi < 4; mi++) {
            int m0 = bm + wm * 64 + mi * 16 + (lane >> 2);
            __half2 h0 = __floats2half2_rn(DEQ * (float)acc[mi][ni][0] + c2a,
                                           DEQ * (float)acc[mi][ni][1] + c2b);
            __half2 h1 = __floats2half2_rn(DEQ * (float)acc[mi][ni][2] + c2a,
                                           DEQ * (float)acc[mi][ni][3] + c2b);
            *reinterpret_cast<__half2*>(&g_scores[(size_t)m0 * CDIM + n0])       = h0;
            *reinterpret_cast<__half2*>(&g_scores[(size_t)(m0 + 8) * CDIM + n0]) = h1;
        }
    }
}

// ---------------- kernel 3: select + exact fp64 rescore ----------------------
#define MARGIN 10.0f
#define MAXCAND 128

__global__ __launch_bounds__(256) void select_rescore(
    const float* __restrict__ x, const float* __restrict__ cb,
    float* __restrict__ out)
{
    __shared__ float  xs[KDIM];
    __shared__ float  smax[8];
    __shared__ double sred[2][8];
    __shared__ int    cand[MAXCAND];
    __shared__ int    ncand;

    const int m    = blockIdx.x;
    const int t    = threadIdx.x;
    const int lane = t & 31;
    const int wrp  = t >> 5;

    {
        const float4* src = reinterpret_cast<const float4*>(x + (size_t)m * KDIM);
        reinterpret_cast<float4*>(xs)[t] = src[t];
    }
    if (t == 0) ncand = 0;

    const uint4* row = reinterpret_cast<const uint4*>(g_scores + (size_t)m * CDIM);
    uint4 v[4];
    float lmax = -3.4e38f;
    #pragma unroll
    for (int j = 0; j < 4; j++) {
        v[j] = row[t + 256 * j];
        const __half2* h = reinterpret_cast<const __half2*>(&v[j]);
        #pragma unroll
        for (int e = 0; e < 4; e++) {
            float2 f = __half22float2(h[e]);
            lmax = fmaxf(lmax, fmaxf(f.x, f.y));
        }
    }
    #pragma unroll
    for (int o = 16; o; o >>= 1)
        lmax = fmaxf(lmax, __shfl_xor_sync(0xffffffffu, lmax, o));
    if (lane == 0) smax[wrp] = lmax;
    __syncthreads();
    float rowmax = smax[0];
    #pragma unroll
    for (int w = 1; w < 8; w++) rowmax = fmaxf(rowmax, smax[w]);
    const float thresh = rowmax - MARGIN;

    #pragma unroll
    for (int j = 0; j < 4; j++) {
        const __half2* h = reinterpret_cast<const __half2*>(&v[j]);
        #pragma unroll
        for (int e = 0; e < 4; e++) {
            float2 f = __half22float2(h[e]);
            int base = (t + 256 * j) * 8 + e * 2;
            if (f.x > thresh) { int p = atomicAdd(&ncand, 1); if (p < MAXCAND) cand[p] = base; }
            if (f.y > thresh) { int p = atomicAdd(&ncand, 1); if (p < MAXCAND) cand[p] = base + 1; }
        }
    }
    __syncthreads();
    int nc = min(ncand, MAXCAND);

    double bestS = -1e300;
    int    bestI = 0x7FFFFFFF;
    for (int ci = 0; ci < nc; ci++) {
        int c = cand[ci];
        const float* crow = cb + (size_t)c * KDIM;
        double s = 0.0, cc = 0.0;
        for (int d = t; d < KDIM; d += 256) {
            double cv = (double)crow[d];
            s  += (double)xs[d] * cv;
            cc += cv * cv;
        }
        #pragma unroll
        for (int o = 16; o; o >>= 1) {
            s  += __shfl_xor_sync(0xffffffffu, s,  o);
            cc += __shfl_xor_sync(0xffffffffu, cc, o);
        }
        if (lane == 0) { sred[0][wrp] = s; sred[1][wrp] = cc; }
        __syncthreads();
        double st = 0.0, ct = 0.0;
        #pragma unroll
        for (int w = 0; w < 8; w++) { st += sred[0][w]; ct += sred[1][w]; }
        __syncthreads();
        double sc = 2.0 * st - ct;
        if (sc > bestS || (sc == bestS && c < bestI)) { bestS = sc; bestI = c; }
    }

    const float4* src = reinterpret_cast<const float4*>(cb + (size_t)bestI * KDIM);
    float4* dst = reinterpret_cast<float4*>(out + (size_t)m * KDIM);
    dst[t] = src[t];
}

// ---------------- launch ------------------------------------------------------
extern "C" void kernel_launch(void* const* d_in, const int* in_sizes, int n_in,
                              void* d_out, int out_size)
{
    const float* x  = (const float*)d_in[0];   // [8192, 1024]
    const float* cb = (const float*)d_in[1];   // [8192, 1024]
    float* out = (float*)d_out;

    const int NX = MDIM * KDIM;
    const int NC = CDIM * KDIM;

    int8_t *x8_p = nullptr, *cb8_p = nullptr;
    cudaGetSymbolAddress((void**)&x8_p, g_x8);
    cudaGetSymbolAddress((void**)&cb8_p, g_cb8);

    cudaFuncSetAttribute(screen_gemm,
                         cudaFuncAttributeMaxDynamicSharedMemorySize, SMEM_TOT);

    convert_s8<<<NX / 2048, 256>>>(x,  x8_p, NX);
    convert_s8<<<NC / 2048, 256>>>(cb, cb8_p, NC);
    c2_kernel<<<CDIM / 8, 256>>>(cb, CDIM, KDIM);

    dim3 grid(CDIM / 128, MDIM / 128);
    screen_gemm<<<grid, 320, SMEM_TOT>>>();

    select_rescore<<<MDIM, 256>>>(x, cb, out);
}

// round 15
// speedup vs baseline: 1.5150x; 1.0006x over previous
#include <cuda_runtime.h>
#include <cuda_fp16.h>
#include <cstdint>

// ---------------------------------------------------------------------------
// CodebookLayer: out[m] = codebook[argmax_c (2*x.c - ||c||^2)]
//
// Round 15: INT8 IMMA screen GEMM with BK=128 (128B rows, SW128 swizzle):
// one mbar_wait per 2048 tensor-cycles of work (4x amortization vs R14).
// Warp-specialized 6->3-stage mbarrier pipeline, s32 exact accumulation.
// Exact fp64 rescore (MARGIN 10) unchanged.
// ---------------------------------------------------------------------------

#define MDIM 8192
#define CDIM 8192
#define KDIM 1024
#define QSCALE 25.0f
#define DEQ (2.0f / (QSCALE * QSCALE))   // 2/625

__device__ __half  g_scores[(size_t)MDIM * CDIM];   // 128 MB scratch
__device__ int8_t  g_x8 [(size_t)MDIM * KDIM];
__device__ int8_t  g_cb8[(size_t)CDIM * KDIM];
__device__ float   g_c2[CDIM];

// ---------------- helpers ---------------------------------------------------
__device__ __forceinline__ uint32_t smem_u32(const void* p) {
    uint32_t a;
    asm("{ .reg .u64 t; cvta.to.shared.u64 t, %1; cvt.u32.u64 %0, t; }"
        : "=r"(a) : "l"(p));
    return a;
}
__device__ __forceinline__ void cp16(uint32_t s, const void* g) {
    asm volatile("cp.async.cg.shared.global [%0], [%1], 16;"
                 :: "r"(s), "l"(g) : "memory");
}
__device__ __forceinline__ void ldsm4(uint32_t* r, uint32_t addr) {
    asm volatile("ldmatrix.sync.aligned.m8n8.x4.shared.b16 {%0,%1,%2,%3}, [%4];"
        : "=r"(r[0]), "=r"(r[1]), "=r"(r[2]), "=r"(r[3]) : "r"(addr));
}
__device__ __forceinline__ void mma_s8(int* d, const uint32_t* a,
                                       uint32_t b0, uint32_t b1) {
    asm volatile(
        "mma.sync.aligned.m16n8k32.row.col.s32.s8.s8.s32 "
        "{%0,%1,%2,%3}, {%4,%5,%6,%7}, {%8,%9}, {%0,%1,%2,%3};"
        : "+r"(d[0]), "+r"(d[1]), "+r"(d[2]), "+r"(d[3])
        : "r"(a[0]), "r"(a[1]), "r"(a[2]), "r"(a[3]), "r"(b0), "r"(b1));
}
__device__ __forceinline__ void mbar_init(uint32_t addr, uint32_t cnt) {
    asm volatile("mbarrier.init.shared.b64 [%0], %1;" :: "r"(addr), "r"(cnt) : "memory");
}
__device__ __forceinline__ void mbar_wait(uint32_t addr, uint32_t parity) {
    asm volatile(
        "{\n\t.reg .pred P;\n"
        "WL_%=:\n\t"
        "mbarrier.try_wait.parity.acquire.cta.shared::cta.b64 P, [%0], %1, 0x989680;\n\t"
        "@P bra WD_%=;\n\t"
        "bra WL_%=;\n"
        "WD_%=:\n\t}"
        :: "r"(addr), "r"(parity) : "memory");
}
__device__ __forceinline__ void mbar_arrive(uint32_t addr) {
    asm volatile("mbarrier.arrive.release.cta.shared::cta.b64 _, [%0];"
                 :: "r"(addr) : "memory");
}
__device__ __forceinline__ void cpasync_mbar_arrive_noinc(uint32_t addr) {
    asm volatile("cp.async.mbarrier.arrive.noinc.shared.b64 [%0];"
                 :: "r"(addr) : "memory");
}

// ---------------- kernel 0: fp32 -> s8 (q = clamp(round(25 v))) --------------
__device__ __forceinline__ uint32_t q4(float4 v) {
    int a = __float2int_rn(v.x * QSCALE);
    int b = __float2int_rn(v.y * QSCALE);
    int c = __float2int_rn(v.z * QSCALE);
    int d = __float2int_rn(v.w * QSCALE);
    a = max(-127, min(127, a)); b = max(-127, min(127, b));
    c = max(-127, min(127, c)); d = max(-127, min(127, d));
    return (uint32_t)(uint8_t)a | ((uint32_t)(uint8_t)b << 8) |
           ((uint32_t)(uint8_t)c << 16) | ((uint32_t)(uint8_t)d << 24);
}
__global__ void convert_s8(const float* __restrict__ s,
                           int8_t* __restrict__ d, int n) {
    int i = (blockIdx.x * blockDim.x + threadIdx.x) * 8;
    if (i >= n) return;
    float4 v0 = *reinterpret_cast<const float4*>(s + i);
    float4 v1 = *reinterpret_cast<const float4*>(s + i + 4);
    uint2 o; o.x = q4(v0); o.y = q4(v1);
    *reinterpret_cast<uint2*>(d + i) = o;
}

// ---------------- kernel 1: codebook row norms (exact fp32) ------------------
__global__ void c2_kernel(const float* __restrict__ cb, int C, int K) {
    int row  = blockIdx.x * (blockDim.x >> 5) + (threadIdx.x >> 5);
    int lane = threadIdx.x & 31;
    if (row >= C) return;
    const float4* p = reinterpret_cast<const float4*>(cb + (size_t)row * K);
    float s = 0.f;
    for (int i = lane; i < (K >> 2); i += 32) {
        float4 v = p[i];
        s += v.x * v.x + v.y * v.y + v.z * v.z + v.w * v.w;
    }
    #pragma unroll
    for (int m = 16; m; m >>= 1) s += __shfl_xor_sync(0xffffffffu, s, m);
    if (lane == 0) g_c2[row] = s;
}

// ---------------- kernel 2: warp-specialized int8 screening GEMM -------------
// BM=BN=128, BK=128 int8 (128B rows, SW128). 320 thr: warps 0-7 consumers
// (64x32 tiles, s32 acc), warps 8 (A) / 9 (B) producers. 3-stage pipeline.
#define NSTAGE 3
#define TILE_BYTES  16384          // 128 rows x 128 B
#define STAGE_BYTES 32768          // A + B
#define NS (KDIM / 128)            // 8 k-stages
#define SMEM_TOT (1024 + NSTAGE * STAGE_BYTES)

__global__ __launch_bounds__(320, 2) void screen_gemm() {
    extern __shared__ __align__(1024) char smem[];
    const uint32_t base  = smem_u32(smem);
    const uint32_t mb    = base;                 // full[s]=+s*16, empty[s]=+s*16+8
    const uint32_t tiles = base + 1024;

    const int t    = threadIdx.x;
    const int lane = t & 31;
    const int wid  = t >> 5;
    const int bm   = blockIdx.y * 128;
    const int bn   = blockIdx.x * 128;

    if (t == 0) {
        #pragma unroll
        for (int s = 0; s < NSTAGE; s++) {
            mbar_init(mb + s * 16,     64);   // full: 2 prod warps x 32 noinc
            mbar_init(mb + s * 16 + 8, 8);    // empty: 8 consumer warp arrivals
        }
    }
    __syncthreads();

    if (wid >= 8) {
        // ================= PRODUCER (warp 8: A tile, warp 9: B tile) ========
        const int pw   = wid - 8;                        // 0=A, 1=B
        const int ch   = lane & 7;                       // 16B chunk 0..7
        const int row0 = lane >> 3;                      // 0..3
        const int8_t* gsrc = (pw == 0)
            ? g_x8  + (size_t)(bm + row0) * KDIM + ch * 16
            : g_cb8 + (size_t)(bn + row0) * KDIM + ch * 16;
        const uint32_t tile_off = (uint32_t)pw * TILE_BYTES;
        const uint32_t rbase = (uint32_t)row0 * 128;
        const uint32_t sw0 = (uint32_t)((ch ^ row0) << 4);        // rows row0+8k
        const uint32_t sw1 = (uint32_t)((ch ^ row0 ^ 4) << 4);    // rows row0+4+8k

        int b = 0, ep = 0;
        for (int s = 0; s < NS; s++) {
            if (s >= NSTAGE) mbar_wait(mb + b * 16 + 8, ep);
            const uint32_t so = tiles + b * STAGE_BYTES + tile_off + rbase;
            const int8_t* g = gsrc + s * 128;
            #pragma unroll
            for (int i = 0; i < 32; i++)                 // rows row0 + 4i
                cp16(so + (uint32_t)i * 512 + ((i & 1) ? sw1 : sw0),
                     g + (size_t)i * 4 * KDIM);
            cpasync_mbar_arrive_noinc(mb + b * 16);
            if (++b == NSTAGE) { b = 0; if (s >= NSTAGE) ep ^= 1; }
        }
        return;                                          // producers done
    }

    // ===================== CONSUMER (warps 0-7, 64x32 tiles) ================
    const int wm = wid >> 2;            // 0..1
    const int wn = wid & 3;             // 0..3
    const int rbase = lane & 15;
    const uint32_t lh = (uint32_t)(lane >> 4);           // 0/1

    // swizzled ldsm offsets for k32-half 0 (half h = off ^ (h<<5))
    uint32_t off[6];
    #pragma unroll
    for (int mi = 0; mi < 4; mi++) {
        int row = wm * 64 + mi * 16 + rbase;
        off[mi] = (uint32_t)row * 128 +
                  ((lh ^ (uint32_t)(row & 7)) << 4);
    }
    #pragma unroll
    for (int g = 0; g < 2; g++) {
        int row = wn * 32 + g * 16 + rbase;
        off[4 + g] = TILE_BYTES + (uint32_t)row * 128 +
                     ((lh ^ (uint32_t)(row & 7)) << 4);
    }

    int acc[4][4][4];
    #pragma unroll
    for (int i = 0; i < 4; i++)
        #pragma unroll
        for (int j = 0; j < 4; j++)
            #pragma unroll
            for (int k = 0; k < 4; k++) acc[i][j][k] = 0;

    uint32_t fa[4][4], fb[2][4];

    #define LOADK(As, x)                                                      \
        {                                                                     \
            ldsm4(fa[0], (As) + (off[0] ^ (x))); ldsm4(fa[1], (As) + (off[1] ^ (x))); \
            ldsm4(fa[2], (As) + (off[2] ^ (x))); ldsm4(fa[3], (As) + (off[3] ^ (x))); \
            ldsm4(fb[0], (As) + (off[4] ^ (x))); ldsm4(fb[1], (As) + (off[5] ^ (x))); \
        }
    #define MMAK()                                                            \
        {                                                                     \
            _Pragma("unroll")                                                 \
            for (int mi = 0; mi < 4; mi++)                                    \
                _Pragma("unroll")                                             \
                for (int ni = 0; ni < 4; ni++)                                \
                    mma_s8(acc[mi][ni], fa[mi],                               \
                           fb[ni >> 1][ni & 1], fb[ni >> 1][(ni & 1) + 2]);   \
        }

    int b = 0, pf = 0;
    for (int s = 0; s < NS; s++) {
        mbar_wait(mb + b * 16, pf);
        const uint32_t As = tiles + b * STAGE_BYTES;

        LOADK(As, 0x00u)  MMAK()                      // k32 half 0
        LOADK(As, 0x20u)  MMAK()                      // k32 half 1
        LOADK(As, 0x40u)  MMAK()                      // k32 half 2
        LOADK(As, 0x60u)                              // k32 half 3
        if (lane == 0) mbar_arrive(mb + b * 16 + 8);  // all stage ldsm done
        MMAK()

        if (++b == NSTAGE) { b = 0; pf ^= 1; }
    }

    // ---- epilogue: score = DEQ*qdot + (1024 - c2), fp16 store ----
    #pragma unroll
    for (int ni = 0; ni < 4; ni++) {
        int n0 = bn + wn * 32 + ni * 8 + 2 * (lane & 3);
        float c2a = 1024.f - g_c2[n0];
        float c2b = 1024.f - g_c2[n0 + 1];
        #pragma unroll
        for (int mi = 0; mi < 4; mi++) {
            int m0 = bm + wm * 64 + mi * 16 + (lane >> 2);
            __half2 h0 = __floats2half2_rn(DEQ * (float)acc[mi][ni][0] + c2a,
                                           DEQ * (float)acc[mi][ni][1] + c2b);
            __half2 h1 = __floats2half2_rn(DEQ * (float)acc[mi][ni][2] + c2a,
                                           DEQ * (float)acc[mi][ni][3] + c2b);
            *reinterpret_cast<__half2*>(&g_scores[(size_t)m0 * CDIM + n0])       = h0;
            *reinterpret_cast<__half2*>(&g_scores[(size_t)(m0 + 8) * CDIM + n0]) = h1;
        }
    }
}

// ---------------- kernel 3: select + exact fp64 rescore ----------------------
#define MARGIN 10.0f
#define MAXCAND 128

__global__ __launch_bounds__(256) void select_rescore(
    const float* __restrict__ x, const float* __restrict__ cb,
    float* __restrict__ out)
{
    __shared__ float  xs[KDIM];
    __shared__ float  smax[8];
    __shared__ double sred[2][8];
    __shared__ int    cand[MAXCAND];
    __shared__ int    ncand;

    const int m    = blockIdx.x;
    const int t    = threadIdx.x;
    const int lane = t & 31;
    const int wrp  = t >> 5;

    {
        const float4* src = reinterpret_cast<const float4*>(x + (size_t)m * KDIM);
        reinterpret_cast<float4*>(xs)[t] = src[t];
    }
    if (t == 0) ncand = 0;

    const uint4* row = reinterpret_cast<const uint4*>(g_scores + (size_t)m * CDIM);
    uint4 v[4];
    float lmax = -3.4e38f;
    #pragma unroll
    for (int j = 0; j < 4; j++) {
        v[j] = row[t + 256 * j];
        const __half2* h = reinterpret_cast<const __half2*>(&v[j]);
        #pragma unroll
        for (int e = 0; e < 4; e++) {
            float2 f = __half22float2(h[e]);
            lmax = fmaxf(lmax, fmaxf(f.x, f.y));
        }
    }
    #pragma unroll
    for (int o = 16; o; o >>= 1)
        lmax = fmaxf(lmax, __shfl_xor_sync(0xffffffffu, lmax, o));
    if (lane == 0) smax[wrp] = lmax;
    __syncthreads();
    float rowmax = smax[0];
    #pragma unroll
    for (int w = 1; w < 8; w++) rowmax = fmaxf(rowmax, smax[w]);
    const float thresh = rowmax - MARGIN;

    #pragma unroll
    for (int j = 0; j < 4; j++) {
        const __half2* h = reinterpret_cast<const __half2*>(&v[j]);
        #pragma unroll
        for (int e = 0; e < 4; e++) {
            float2 f = __half22float2(h[e]);
            int base = (t + 256 * j) * 8 + e * 2;
            if (f.x > thresh) { int p = atomicAdd(&ncand, 1); if (p < MAXCAND) cand[p] = base; }
            if (f.y > thresh) { int p = atomicAdd(&ncand, 1); if (p < MAXCAND) cand[p] = base + 1; }
        }
    }
    __syncthreads();
    int nc = min(ncand, MAXCAND);

    double bestS = -1e300;
    int    bestI = 0x7FFFFFFF;
    for (int ci = 0; ci < nc; ci++) {
        int c = cand[ci];
        const float* crow = cb + (size_t)c * KDIM;
        double s = 0.0, cc = 0.0;
        for (int d = t; d < KDIM; d += 256) {
            double cv = (double)crow[d];
            s  += (double)xs[d] * cv;
            cc += cv * cv;
        }
        #pragma unroll
        for (int o = 16; o; o >>= 1) {
            s  += __shfl_xor_sync(0xffffffffu, s,  o);
            cc += __shfl_xor_sync(0xffffffffu, cc, o);
        }
        if (lane == 0) { sred[0][wrp] = s; sred[1][wrp] = cc; }
        __syncthreads();
        double st = 0.0, ct = 0.0;
        #pragma unroll
        for (int w = 0; w < 8; w++) { st += sred[0][w]; ct += sred[1][w]; }
        __syncthreads();
        double sc = 2.0 * st - ct;
        if (sc > bestS || (sc == bestS && c < bestI)) { bestS = sc; bestI = c; }
    }

    const float4* src = reinterpret_cast<const float4*>(cb + (size_t)bestI * KDIM);
    float4* dst = reinterpret_cast<float4*>(out + (size_t)m * KDIM);
    dst[t] = src[t];
}

// ---------------- launch ------------------------------------------------------
extern "C" void kernel_launch(void* const* d_in, const int* in_sizes, int n_in,
                              void* d_out, int out_size)
{
    const float* x  = (const float*)d_in[0];   // [8192, 1024]
    const float* cb = (const float*)d_in[1];   // [8192, 1024]
    float* out = (float*)d_out;

    const int NX = MDIM * KDIM;
    const int NC = CDIM * KDIM;

    int8_t *x8_p = nullptr, *cb8_p = nullptr;
    cudaGetSymbolAddress((void**)&x8_p, g_x8);
    cudaGetSymbolAddress((void**)&cb8_p, g_cb8);

    cudaFuncSetAttribute(screen_gemm,
                         cudaFuncAttributeMaxDynamicSharedMemorySize, SMEM_TOT);

    convert_s8<<<NX / 2048, 256>>>(x,  x8_p, NX);
    convert_s8<<<NC / 2048, 256>>>(cb, cb8_p, NC);
    c2_kernel<<<CDIM / 8, 256>>>(cb, CDIM, KDIM);

    dim3 grid(CDIM / 128, MDIM / 128);
    screen_gemm<<<grid, 320, SMEM_TOT>>>();

    select_rescore<<<MDIM, 256>>>(x, cb, out);
}